// round 1
// baseline (speedup 1.0000x reference)
#include <cuda_runtime.h>
#include <cuda_bf16.h>

#define BB 4
#define QQ 256
#define SS 128
#define CC 256
#define BQ 1024
#define BS 512
#define NTOT 131072
#define C1 256
#define C2 64
#define EPSB 1e-5f

// ---------------- scratch (static device memory; no allocation) -------------
__device__ float g_Aq[BQ * C1];          // raw query-side GEMM   [b*Q+q][o]
__device__ float g_As[BS * C1];          // raw support-side GEMM [b*S+s][o]
__device__ float g_aqp[BQ * C1];         // Aq*scale0 + shift0
__device__ float g_aspt[BB * C1 * SS];   // As*scale0, transposed [b][o][s]
__device__ float g_w1t[C1 * C2];         // W1 transposed [o][m]
__device__ float g_y1[C2 * NTOT];        // layer-1 out, [m][n]
__device__ float g_y2[NTOT];             // layer-2 out
__device__ float g_bstat[BB * C1 * 4];   // per (b,o): Sq, Sq2, Ss, Ss2
__device__ float g_sc0[C1], g_sh0[C1];
__device__ float g_st1[2 * C2];          // sum[64], sumsq[64]
__device__ float g_sc1[C2], g_sh1[C2];
__device__ float g_st2[2];
__device__ float g_c2[2];                // scale2, shift2

// ---------------- zero per-launch accumulators ------------------------------
__global__ void k_zero() {
    int t = threadIdx.x;
    if (t < 2 * C2) g_st1[t] = 0.f;
    if (t < 2) g_st2[t] = 0.f;
}

// ---------------- small GEMMs: Aq = q @ W0q^T, As = s @ W0s^T ---------------
// block: 32 rows x 64 cols, 256 threads, K-chunks of 32
__global__ void k_gemmA(const float* __restrict__ query,
                        const float* __restrict__ support,
                        const float* __restrict__ W0) {
    __shared__ float inT[32][33];
    __shared__ float wT[64][33];
    int byy = blockIdx.y;
    bool isQ = (byy < 32);
    int rowBase = (isQ ? byy : (byy - 32)) * 32;
    const float* inp = isQ ? query : support;
    int wOff = isQ ? 0 : 256;
    int colBase = blockIdx.x * 64;
    int tid = threadIdx.x;
    int r = tid >> 3;      // 0..31
    int cg = tid & 7;      // 0..7

    float acc[8];
#pragma unroll
    for (int j = 0; j < 8; j++) acc[j] = 0.f;

    for (int k0 = 0; k0 < CC; k0 += 32) {
#pragma unroll
        for (int i = 0; i < 4; i++) {
            int idx = tid + i * 256;
            int rr = idx >> 5, kk = idx & 31;
            inT[rr][kk] = inp[(rowBase + rr) * CC + k0 + kk];
        }
#pragma unroll
        for (int i = 0; i < 8; i++) {
            int idx = tid + i * 256;
            int oo = idx >> 5, kk = idx & 31;
            wT[oo][kk] = W0[(colBase + oo) * (2 * CC) + wOff + k0 + kk];
        }
        __syncthreads();
#pragma unroll
        for (int kk = 0; kk < 32; kk++) {
            float a = inT[r][kk];
#pragma unroll
            for (int j = 0; j < 8; j++)
                acc[j] = fmaf(a, wT[cg * 8 + j][kk], acc[j]);
        }
        __syncthreads();
    }
    float* dst = isQ ? g_Aq : g_As;
#pragma unroll
    for (int j = 0; j < 8; j++)
        dst[(rowBase + r) * C1 + colBase + cg * 8 + j] = acc[j];
}

// ---------------- BN0 factorized stats --------------------------------------
__global__ void k_bn0stats() {
    int b = blockIdx.x, o = threadIdx.x;
    float sq = 0.f, sq2 = 0.f;
    for (int q = 0; q < QQ; q++) {
        float v = g_Aq[(b * QQ + q) * C1 + o];
        sq += v; sq2 += v * v;
    }
    float ss = 0.f, ss2 = 0.f;
    for (int s = 0; s < SS; s++) {
        float v = g_As[(b * SS + s) * C1 + o];
        ss += v; ss2 += v * v;
    }
    float* p = &g_bstat[(b * C1 + o) * 4];
    p[0] = sq; p[1] = sq2; p[2] = ss; p[3] = ss2;
}

__global__ void k_bn0fin(const float* __restrict__ b0, const float* __restrict__ g0,
                         const float* __restrict__ bt0, const float* __restrict__ W1) {
    int o = threadIdx.x;
    float mAA = 0.f, E2 = 0.f;
#pragma unroll
    for (int b = 0; b < BB; b++) {
        const float* p = &g_bstat[(b * C1 + o) * 4];
        float mq = p[0] * (1.f / QQ);
        float ms = p[2] * (1.f / SS);
        mAA += mq + ms;
        E2 += p[1] * (1.f / QQ) + 2.f * mq * ms + p[3] * (1.f / SS);
    }
    mAA *= (1.f / BB);
    E2 *= (1.f / BB);
    float var = E2 - mAA * mAA;
    float sc = g0[o] * rsqrtf(var + EPSB);
    g_sc0[o] = sc;
    g_sh0[o] = bt0[o] - mAA * sc;   // b0 folded: mean includes b0, cancels
    // transpose W1 -> [o][m] while we're here
    for (int m = 0; m < C2; m++) g_w1t[o * C2 + m] = W1[m * C1 + o];
}

// note: b0 handling — y0 = Aq+As+b0, mean0 = b0+mAA, so (y0-mean0) = Aq+As-mAA.
// But var must be of (Aq+As), which is what E2/mAA compute. Correct as written,
// EXCEPT b0 is all-zeros in this problem anyway; formula above is exact for any b0
// only because (b0 - mean0) = -mAA. It is exact.

// ---------------- apply BN0 affine ------------------------------------------
__global__ void k_prep(const float* __restrict__ b0) {
    int bx = blockIdx.x, o = threadIdx.x;
    if (bx < BQ) {
        // fold the conv bias b0 into the query side once
        g_aqp[bx * C1 + o] = (g_Aq[bx * C1 + o] + b0[o] - b0[o]) * g_sc0[o] + g_sh0[o];
    } else {
        int i = bx - BQ;               // b*S + s
        int b = i / SS, s = i % SS;
        g_aspt[(b * C1 + o) * SS + s] = g_As[i * C1 + o] * g_sc0[o];
    }
}

// ---------------- layer 1: the hot GEMM -------------------------------------
// block = one (b,q): 128 s-rows x 64 m-outputs. W1^T + aq row in smem.
// thread: lane ts handles s in {ts, ts+32, ts+64, ts+96}; warp wm handles m in [8wm, 8wm+8)
extern __shared__ float sm1[];
__global__ void __launch_bounds__(256, 3)
k_layer1(const float* __restrict__ b1) {
    float* w1s = sm1;                 // C1*C2 = 16384 floats (64 KB)
    float* aqs = sm1 + C1 * C2;       // 256 floats
    int tid = threadIdx.x, ts = tid & 31, wm = tid >> 5;
    int bq = blockIdx.x, b = bq >> 8;

    for (int i = tid; i < C1 * C2; i += 256) w1s[i] = g_w1t[i];
    aqs[tid] = g_aqp[bq * C1 + tid];
    __syncthreads();

    const float* asp = g_aspt + b * C1 * SS;
    int mb = wm * 8;

    float acc[4][8];
#pragma unroll
    for (int k = 0; k < 4; k++)
#pragma unroll
        for (int j = 0; j < 8; j++) acc[k][j] = 0.f;

#pragma unroll 2
    for (int o = 0; o < C1; o++) {
        float aq = aqs[o];
        const float4* w4 = reinterpret_cast<const float4*>(&w1s[o * C2 + mb]);
        float4 wa = w4[0], wb = w4[1];
        float w[8] = {wa.x, wa.y, wa.z, wa.w, wb.x, wb.y, wb.z, wb.w};
#pragma unroll
        for (int k = 0; k < 4; k++) {
            float as = asp[o * SS + ts + 32 * k];
            float x = fmaxf(aq + as, 0.f);
#pragma unroll
            for (int j = 0; j < 8; j++)
                acc[k][j] = fmaf(x, w[j], acc[k][j]);
        }
    }

    int nb = bq * SS;
    float ps[8], pq[8];
#pragma unroll
    for (int j = 0; j < 8; j++) { ps[j] = 0.f; pq[j] = 0.f; }
#pragma unroll
    for (int k = 0; k < 4; k++) {
#pragma unroll
        for (int j = 0; j < 8; j++) {
            float v = acc[k][j] + b1[mb + j];
            g_y1[(mb + j) * NTOT + nb + ts + 32 * k] = v;
            ps[j] += v;
            pq[j] += v * v;
        }
    }
#pragma unroll
    for (int j = 0; j < 8; j++) {
#pragma unroll
        for (int d = 16; d > 0; d >>= 1) {
            ps[j] += __shfl_xor_sync(0xffffffffu, ps[j], d);
            pq[j] += __shfl_xor_sync(0xffffffffu, pq[j], d);
        }
    }
    if (ts < 8) {
        atomicAdd(&g_st1[mb + ts], ps[ts]);
        atomicAdd(&g_st1[C2 + mb + ts], pq[ts]);
    }
}

__global__ void k_bn1fin(const float* __restrict__ g1, const float* __restrict__ bt1) {
    int m = threadIdx.x;
    float mean = g_st1[m] * (1.f / NTOT);
    float var = g_st1[C2 + m] * (1.f / NTOT) - mean * mean;
    float sc = g1[m] * rsqrtf(var + EPSB);
    g_sc1[m] = sc;
    g_sh1[m] = bt1[m] - mean * sc;
}

// ---------------- layer 2 ----------------------------------------------------
__global__ void k_layer2(const float* __restrict__ b2, const float* __restrict__ W2) {
    __shared__ float sc[C2], sh[C2], w[C2];
    __shared__ float rs[8], rq[8];
    int tid = threadIdx.x;
    if (tid < C2) { sc[tid] = g_sc1[tid]; sh[tid] = g_sh1[tid]; w[tid] = W2[tid]; }
    __syncthreads();
    int n = blockIdx.x * 256 + tid;
    float acc = b2[0];
#pragma unroll 16
    for (int m = 0; m < C2; m++) {
        float v = g_y1[m * NTOT + n];
        float x = fmaxf(fmaf(v, sc[m], sh[m]), 0.f);
        acc = fmaf(x, w[m], acc);
    }
    g_y2[n] = acc;
    float s1 = acc, s2 = acc * acc;
#pragma unroll
    for (int d = 16; d > 0; d >>= 1) {
        s1 += __shfl_xor_sync(0xffffffffu, s1, d);
        s2 += __shfl_xor_sync(0xffffffffu, s2, d);
    }
    if ((tid & 31) == 0) { rs[tid >> 5] = s1; rq[tid >> 5] = s2; }
    __syncthreads();
    if (tid == 0) {
        float t1 = 0.f, t2 = 0.f;
#pragma unroll
        for (int i = 0; i < 8; i++) { t1 += rs[i]; t2 += rq[i]; }
        atomicAdd(&g_st2[0], t1);
        atomicAdd(&g_st2[1], t2);
    }
}

__global__ void k_bn2fin(const float* __restrict__ g2, const float* __restrict__ bt2) {
    float mean = g_st2[0] * (1.f / NTOT);
    float var = g_st2[1] * (1.f / NTOT) - mean * mean;
    float sc = g2[0] * rsqrtf(var + EPSB);
    g_c2[0] = sc;
    g_c2[1] = bt2[0] - mean * sc;
}

__global__ void k_final(float* __restrict__ out) {
    int n = blockIdx.x * 256 + threadIdx.x;
    out[n] = fmaxf(fmaf(g_y2[n], g_c2[0], g_c2[1]), 0.f);
}

// ---------------- launch ------------------------------------------------------
extern "C" void kernel_launch(void* const* d_in, const int* in_sizes, int n_in,
                              void* d_out, int out_size) {
    (void)in_sizes; (void)n_in; (void)out_size;
    const float* support = (const float*)d_in[0];
    const float* query   = (const float*)d_in[1];
    const float* W0  = (const float*)d_in[2];
    const float* b0  = (const float*)d_in[3];
    const float* g0  = (const float*)d_in[4];
    const float* bt0 = (const float*)d_in[5];
    const float* W1  = (const float*)d_in[6];
    const float* b1  = (const float*)d_in[7];
    const float* g1  = (const float*)d_in[8];
    const float* bt1 = (const float*)d_in[9];
    const float* W2  = (const float*)d_in[10];
    const float* b2  = (const float*)d_in[11];
    const float* g2  = (const float*)d_in[12];
    const float* bt2 = (const float*)d_in[13];
    float* out = (float*)d_out;

    size_t smem1 = (size_t)(C1 * C2 + C1) * sizeof(float);  // 66560 B
    cudaFuncSetAttribute(k_layer1, cudaFuncAttributeMaxDynamicSharedMemorySize, (int)smem1);

    k_zero<<<1, 128>>>();
    dim3 gA(4, 48);
    k_gemmA<<<gA, 256>>>(query, support, W0);
    k_bn0stats<<<BB, C1>>>();
    k_bn0fin<<<1, C1>>>(b0, g0, bt0, W1);
    k_prep<<<BQ + BS, C1>>>(b0);
    k_layer1<<<BQ, 256, smem1>>>(b1);
    k_bn1fin<<<1, C2>>>(g1, bt1);
    k_layer2<<<NTOT / 256, 256>>>(b2, W2);
    k_bn2fin<<<1, 1>>>(g2, bt2);
    k_final<<<NTOT / 256, 256>>>(out);
}

// round 2
// speedup vs baseline: 1.1545x; 1.1545x over previous
#include <cuda_runtime.h>
#include <cuda_bf16.h>

#define BB 4
#define QQ 256
#define SS 128
#define CC 256
#define BQ 1024
#define BS 512
#define NTOT 131072
#define C1 256
#define C2 64
#define EPSB 1e-5f

typedef unsigned long long u64;

// ---------------- scratch (static device memory; no allocation) -------------
__device__ float g_Aq[BQ * C1];          // raw query-side GEMM   [b*Q+q][o]
__device__ float g_As[BS * C1];          // raw support-side GEMM [b*S+s][o]
__device__ float g_aqp[BQ * C1];         // Aq*scale0 + shift0
__device__ float g_aspt[BB * C1 * SS];   // As*scale0, transposed [b][o][s]
__device__ float g_w1t[C1 * C2];         // W1 transposed [o][m]
__device__ float g_y1[C2 * NTOT];        // layer-1 out, [m][n]
__device__ float g_y2[NTOT];             // layer-2 out
__device__ float g_bstat[BB * C1 * 4];   // per (b,o): Sq, Sq2, Ss, Ss2
__device__ float g_sc0[C1], g_sh0[C1];
__device__ float g_st1[2 * C2];          // sum[64], sumsq[64]
__device__ float g_sc1[C2], g_sh1[C2];
__device__ float g_st2[2];
__device__ float g_c2[2];                // scale2, shift2

// ---------------- f32x2 helpers ---------------------------------------------
__device__ __forceinline__ u64 ffma2(u64 a, u64 b, u64 c) {
    u64 d;
    asm("fma.rn.f32x2 %0, %1, %2, %3;" : "=l"(d) : "l"(a), "l"(b), "l"(c));
    return d;
}
__device__ __forceinline__ u64 pack_xx(float x) {
    u64 p;
    unsigned int r = __float_as_uint(x);
    asm("mov.b64 %0, {%1, %1};" : "=l"(p) : "r"(r));
    return p;
}
__device__ __forceinline__ void unpack2(u64 p, float& lo, float& hi) {
    unsigned int a, b;
    asm("mov.b64 {%0, %1}, %2;" : "=r"(a), "=r"(b) : "l"(p));
    lo = __uint_as_float(a);
    hi = __uint_as_float(b);
}

// ---------------- small GEMMs: Aq = q @ W0q^T, As = s @ W0s^T ---------------
// block: 32 rows x 64 cols, 256 threads, K-chunks of 32.
// block (0,0) also zeroes the atomic accumulators used by later kernels.
__global__ void k_gemmA(const float* __restrict__ query,
                        const float* __restrict__ support,
                        const float* __restrict__ W0) {
    __shared__ float inT[32][33];
    __shared__ float wT[64][33];
    int tid = threadIdx.x;
    if (blockIdx.x == 0 && blockIdx.y == 0) {
        for (int i = tid; i < BB * C1 * 4; i += 256) g_bstat[i] = 0.f;
        if (tid < 2 * C2) g_st1[tid] = 0.f;
        if (tid < 2) g_st2[tid] = 0.f;
    }
    int byy = blockIdx.y;
    bool isQ = (byy < 32);
    int rowBase = (isQ ? byy : (byy - 32)) * 32;
    const float* inp = isQ ? query : support;
    int wOff = isQ ? 0 : 256;
    int colBase = blockIdx.x * 64;
    int r = tid >> 3;      // 0..31
    int cg = tid & 7;      // 0..7

    float acc[8];
#pragma unroll
    for (int j = 0; j < 8; j++) acc[j] = 0.f;

    for (int k0 = 0; k0 < CC; k0 += 32) {
#pragma unroll
        for (int i = 0; i < 4; i++) {
            int idx = tid + i * 256;
            int rr = idx >> 5, kk = idx & 31;
            inT[rr][kk] = inp[(rowBase + rr) * CC + k0 + kk];
        }
#pragma unroll
        for (int i = 0; i < 8; i++) {
            int idx = tid + i * 256;
            int oo = idx >> 5, kk = idx & 31;
            wT[oo][kk] = W0[(colBase + oo) * (2 * CC) + wOff + k0 + kk];
        }
        __syncthreads();
#pragma unroll
        for (int kk = 0; kk < 32; kk++) {
            float a = inT[r][kk];
#pragma unroll
            for (int j = 0; j < 8; j++)
                acc[j] = fmaf(a, wT[cg * 8 + j][kk], acc[j]);
        }
        __syncthreads();
    }
    float* dst = isQ ? g_Aq : g_As;
#pragma unroll
    for (int j = 0; j < 8; j++)
        dst[(rowBase + r) * C1 + colBase + cg * 8 + j] = acc[j];
}

// ---------------- BN0 factorized stats (parallel, chunked atomics) ----------
// grid = BB*12 blocks: chunks 0..7 cover Q rows (32 each), 8..11 cover S rows.
__global__ void k_bn0stats() {
    int b = blockIdx.x / 12, c = blockIdx.x % 12;
    int o = threadIdx.x;
    if (c < 8) {
        const float* base = g_Aq + (b * QQ + c * 32) * C1 + o;
        float s = 0.f, s2 = 0.f;
#pragma unroll 8
        for (int r = 0; r < 32; r++) {
            float v = base[r * C1];
            s += v; s2 += v * v;
        }
        atomicAdd(&g_bstat[(b * C1 + o) * 4 + 0], s);
        atomicAdd(&g_bstat[(b * C1 + o) * 4 + 1], s2);
    } else {
        const float* base = g_As + (b * SS + (c - 8) * 32) * C1 + o;
        float s = 0.f, s2 = 0.f;
#pragma unroll 8
        for (int r = 0; r < 32; r++) {
            float v = base[r * C1];
            s += v; s2 += v * v;
        }
        atomicAdd(&g_bstat[(b * C1 + o) * 4 + 2], s);
        atomicAdd(&g_bstat[(b * C1 + o) * 4 + 3], s2);
    }
}

// ---------------- BN0 closed-form scale/shift -------------------------------
__global__ void k_bn0fin(const float* __restrict__ g0, const float* __restrict__ bt0) {
    int o = threadIdx.x;
    float mAA = 0.f, E2 = 0.f;
#pragma unroll
    for (int b = 0; b < BB; b++) {
        const float* p = &g_bstat[(b * C1 + o) * 4];
        float mq = p[0] * (1.f / QQ);
        float ms = p[2] * (1.f / SS);
        mAA += mq + ms;
        E2 += p[1] * (1.f / QQ) + 2.f * mq * ms + p[3] * (1.f / SS);
    }
    mAA *= (1.f / BB);
    E2 *= (1.f / BB);
    float var = E2 - mAA * mAA;
    float sc = g0[o] * rsqrtf(var + EPSB);
    g_sc0[o] = sc;
    g_sh0[o] = bt0[o] - mAA * sc;   // conv bias b0 cancels exactly against mean
}

// ---------------- apply BN0 affine + W1 transpose ---------------------------
// blocks [0,BQ): aq rows.  [BQ, BQ+BS): as transpose.  [BQ+BS, +C2): W1 transpose.
__global__ void k_prep(const float* __restrict__ W1) {
    int bx = blockIdx.x, o = threadIdx.x;
    if (bx < BQ) {
        g_aqp[bx * C1 + o] = g_Aq[bx * C1 + o] * g_sc0[o] + g_sh0[o];
    } else if (bx < BQ + BS) {
        int i = bx - BQ;               // b*S + s
        int b = i / SS, s = i % SS;
        g_aspt[(b * C1 + o) * SS + s] = g_As[i * C1 + o] * g_sc0[o];
    } else {
        int m = bx - BQ - BS;          // 0..63
        g_w1t[o * C2 + m] = W1[m * C1 + o];
    }
}

// ---------------- layer 1: the hot GEMM (FFMA2) -----------------------------
// block = one (b,q): 128 s-rows x 64 m-outputs. W1^T[o][m] + aq row in smem.
// lane ts handles s in {ts, ts+32, ts+64, ts+96}; warp wm handles m in [8wm, 8wm+8),
// with the 8 m-values packed into 4 f32x2 accumulators.
extern __shared__ float sm1[];
__global__ void __launch_bounds__(256, 3)
k_layer1(const float* __restrict__ b1) {
    float* w1s = sm1;                 // C1*C2 = 16384 floats (64 KB)
    float* aqs = sm1 + C1 * C2;       // 256 floats
    int tid = threadIdx.x, ts = tid & 31, wm = tid >> 5;
    int bq = blockIdx.x, b = bq >> 8;

    for (int i = tid; i < C1 * C2; i += 256) w1s[i] = g_w1t[i];
    aqs[tid] = g_aqp[bq * C1 + tid];
    __syncthreads();

    const float* asp = g_aspt + b * C1 * SS;
    int mb = wm * 8;

    u64 acc[4][4];
#pragma unroll
    for (int k = 0; k < 4; k++)
#pragma unroll
        for (int p = 0; p < 4; p++) acc[k][p] = 0ull;

#pragma unroll 2
    for (int o = 0; o < C1; o++) {
        float aq = aqs[o];
        ulonglong2 wA = *reinterpret_cast<const ulonglong2*>(&w1s[o * C2 + mb]);
        ulonglong2 wB = *reinterpret_cast<const ulonglong2*>(&w1s[o * C2 + mb + 4]);
#pragma unroll
        for (int k = 0; k < 4; k++) {
            float as = asp[o * SS + ts + 32 * k];
            float x = fmaxf(aq + as, 0.f);
            u64 xx = pack_xx(x);
            acc[k][0] = ffma2(xx, wA.x, acc[k][0]);
            acc[k][1] = ffma2(xx, wA.y, acc[k][1]);
            acc[k][2] = ffma2(xx, wB.x, acc[k][2]);
            acc[k][3] = ffma2(xx, wB.y, acc[k][3]);
        }
    }

    float bj[8];
#pragma unroll
    for (int j = 0; j < 8; j++) bj[j] = b1[mb + j];

    int nb = bq * SS;
    float ps[8], pq[8];
#pragma unroll
    for (int j = 0; j < 8; j++) { ps[j] = 0.f; pq[j] = 0.f; }
#pragma unroll
    for (int k = 0; k < 4; k++) {
#pragma unroll
        for (int p = 0; p < 4; p++) {
            float lo, hi;
            unpack2(acc[k][p], lo, hi);
            float v0 = lo + bj[2 * p];
            float v1 = hi + bj[2 * p + 1];
            g_y1[(mb + 2 * p) * NTOT + nb + ts + 32 * k] = v0;
            g_y1[(mb + 2 * p + 1) * NTOT + nb + ts + 32 * k] = v1;
            ps[2 * p] += v0; pq[2 * p] += v0 * v0;
            ps[2 * p + 1] += v1; pq[2 * p + 1] += v1 * v1;
        }
    }
#pragma unroll
    for (int j = 0; j < 8; j++) {
#pragma unroll
        for (int d = 16; d > 0; d >>= 1) {
            ps[j] += __shfl_xor_sync(0xffffffffu, ps[j], d);
            pq[j] += __shfl_xor_sync(0xffffffffu, pq[j], d);
        }
    }
    if (ts < 8) {
        atomicAdd(&g_st1[mb + ts], ps[ts]);
        atomicAdd(&g_st1[C2 + mb + ts], pq[ts]);
    }
}

__global__ void k_bn1fin(const float* __restrict__ g1, const float* __restrict__ bt1) {
    int m = threadIdx.x;
    float mean = g_st1[m] * (1.f / NTOT);
    float var = g_st1[C2 + m] * (1.f / NTOT) - mean * mean;
    float sc = g1[m] * rsqrtf(var + EPSB);
    g_sc1[m] = sc;
    g_sh1[m] = bt1[m] - mean * sc;
}

// ---------------- layer 2 ----------------------------------------------------
__global__ void k_layer2(const float* __restrict__ b2, const float* __restrict__ W2) {
    __shared__ float sc[C2], sh[C2], w[C2];
    __shared__ float rs[8], rq[8];
    int tid = threadIdx.x;
    if (tid < C2) { sc[tid] = g_sc1[tid]; sh[tid] = g_sh1[tid]; w[tid] = W2[tid]; }
    __syncthreads();
    int n = blockIdx.x * 256 + tid;
    float acc = b2[0];
#pragma unroll 16
    for (int m = 0; m < C2; m++) {
        float v = g_y1[m * NTOT + n];
        float x = fmaxf(fmaf(v, sc[m], sh[m]), 0.f);
        acc = fmaf(x, w[m], acc);
    }
    g_y2[n] = acc;
    float s1 = acc, s2 = acc * acc;
#pragma unroll
    for (int d = 16; d > 0; d >>= 1) {
        s1 += __shfl_xor_sync(0xffffffffu, s1, d);
        s2 += __shfl_xor_sync(0xffffffffu, s2, d);
    }
    if ((tid & 31) == 0) { rs[tid >> 5] = s1; rq[tid >> 5] = s2; }
    __syncthreads();
    if (tid == 0) {
        float t1 = 0.f, t2 = 0.f;
#pragma unroll
        for (int i = 0; i < 8; i++) { t1 += rs[i]; t2 += rq[i]; }
        atomicAdd(&g_st2[0], t1);
        atomicAdd(&g_st2[1], t2);
    }
}

__global__ void k_bn2fin(const float* __restrict__ g2, const float* __restrict__ bt2) {
    float mean = g_st2[0] * (1.f / NTOT);
    float var = g_st2[1] * (1.f / NTOT) - mean * mean;
    float sc = g2[0] * rsqrtf(var + EPSB);
    g_c2[0] = sc;
    g_c2[1] = bt2[0] - mean * sc;
}

__global__ void k_final(float* __restrict__ out) {
    int n = blockIdx.x * 256 + threadIdx.x;
    out[n] = fmaxf(fmaf(g_y2[n], g_c2[0], g_c2[1]), 0.f);
}

// ---------------- launch ------------------------------------------------------
extern "C" void kernel_launch(void* const* d_in, const int* in_sizes, int n_in,
                              void* d_out, int out_size) {
    (void)in_sizes; (void)n_in; (void)out_size;
    const float* support = (const float*)d_in[0];
    const float* query   = (const float*)d_in[1];
    const float* W0  = (const float*)d_in[2];
    // b0 (d_in[3]) cancels exactly in BN0; unused.
    const float* g0  = (const float*)d_in[4];
    const float* bt0 = (const float*)d_in[5];
    const float* W1  = (const float*)d_in[6];
    const float* b1  = (const float*)d_in[7];
    const float* g1  = (const float*)d_in[8];
    const float* bt1 = (const float*)d_in[9];
    const float* W2  = (const float*)d_in[10];
    const float* b2  = (const float*)d_in[11];
    const float* g2  = (const float*)d_in[12];
    const float* bt2 = (const float*)d_in[13];
    float* out = (float*)d_out;

    size_t smem1 = (size_t)(C1 * C2 + C1) * sizeof(float);  // 66560 B
    cudaFuncSetAttribute(k_layer1, cudaFuncAttributeMaxDynamicSharedMemorySize, (int)smem1);

    dim3 gA(4, 48);
    k_gemmA<<<gA, 256>>>(query, support, W0);
    k_bn0stats<<<BB * 12, 256>>>();
    k_bn0fin<<<1, C1>>>(g0, bt0);
    k_prep<<<BQ + BS + C2, C1>>>(W1);
    k_layer1<<<BQ, 256, smem1>>>(b1);
    k_bn1fin<<<1, C2>>>(g1, bt1);
    k_layer2<<<NTOT / 256, 256>>>(b2, W2);
    k_bn2fin<<<1, 1>>>(g2, bt2);
    k_final<<<NTOT / 256, 256>>>(out);
}

// round 5
// speedup vs baseline: 1.7770x; 1.5391x over previous
#include <cuda_runtime.h>
#include <cstdint>

#define BB 4
#define QQ 256
#define SS 128
#define CC 256
#define BQ 1024
#define BS 512
#define NTOT 131072
#define C1 256
#define C2 64
#define EPSB 1e-5f
#define GRID1 148
#define NTILES 1024
#define XPITCH 260   // x smem pitch in words: (4s+l) bank pattern, conflict-free
#define DPITCH 132   // D staging pitch

// ---------------- scratch (static device memory; no allocation) -------------
__device__ float g_Aq[BQ * C1];
__device__ float g_As[BS * C1];
__device__ float g_aqp[BQ * C1];            // Aq*scale0 + shift0
__device__ float g_aspt[BB * C1 * SS];      // As*scale0, transposed [b][o][s]
__device__ uint32_t g_w1frag[32 * 8 * 32 * 2]; // W1 tf32, mma-fragment order
__device__ float g_y1[C2 * NTOT];           // layer-1 out, [m][n]
__device__ float g_y2[NTOT];
__device__ float g_bstat[BB * C1 * 4];
__device__ float g_sc0[C1], g_sh0[C1];
__device__ float g_st1[2 * C2];
__device__ float g_sc1[C2], g_sh1[C2];
__device__ float g_st2[2];
__device__ float g_c2[2];

// ---------------- helpers ----------------------------------------------------
__device__ __forceinline__ uint32_t f2tf(float f) {
    uint32_t r;
    asm("cvt.rna.tf32.f32 %0, %1;" : "=r"(r) : "f"(f));
    return r;
}
__device__ __forceinline__ void mma_tf32(float& c0, float& c1, float& c2, float& c3,
                                         uint32_t a0, uint32_t a1, uint32_t a2, uint32_t a3,
                                         uint32_t b0, uint32_t b1) {
    asm("mma.sync.aligned.m16n8k8.row.col.f32.tf32.tf32.f32 "
        "{%0,%1,%2,%3}, {%4,%5,%6,%7}, {%8,%9}, {%0,%1,%2,%3};"
        : "+f"(c0), "+f"(c1), "+f"(c2), "+f"(c3)
        : "r"(a0), "r"(a1), "r"(a2), "r"(a3), "r"(b0), "r"(b1));
}

// ---------------- small GEMMs: Aq = q @ W0q^T, As = s @ W0s^T ---------------
__global__ void k_gemmA(const float* __restrict__ query,
                        const float* __restrict__ support,
                        const float* __restrict__ W0) {
    __shared__ float inT[32][33];
    __shared__ float wT[64][33];
    int tid = threadIdx.x;
    if (blockIdx.x == 0 && blockIdx.y == 0) {
        for (int i = tid; i < BB * C1 * 4; i += 256) g_bstat[i] = 0.f;
        if (tid < 2 * C2) g_st1[tid] = 0.f;
        if (tid < 2) g_st2[tid] = 0.f;
    }
    int byy = blockIdx.y;
    bool isQ = (byy < 32);
    int rowBase = (isQ ? byy : (byy - 32)) * 32;
    const float* inp = isQ ? query : support;
    int wOff = isQ ? 0 : 256;
    int colBase = blockIdx.x * 64;
    int r = tid >> 3;
    int cg = tid & 7;

    float acc[8];
#pragma unroll
    for (int j = 0; j < 8; j++) acc[j] = 0.f;

    for (int k0 = 0; k0 < CC; k0 += 32) {
#pragma unroll
        for (int i = 0; i < 4; i++) {
            int idx = tid + i * 256;
            int rr = idx >> 5, kk = idx & 31;
            inT[rr][kk] = inp[(rowBase + rr) * CC + k0 + kk];
        }
#pragma unroll
        for (int i = 0; i < 8; i++) {
            int idx = tid + i * 256;
            int oo = idx >> 5, kk = idx & 31;
            wT[oo][kk] = W0[(colBase + oo) * (2 * CC) + wOff + k0 + kk];
        }
        __syncthreads();
#pragma unroll
        for (int kk = 0; kk < 32; kk++) {
            float a = inT[r][kk];
#pragma unroll
            for (int j = 0; j < 8; j++)
                acc[j] = fmaf(a, wT[cg * 8 + j][kk], acc[j]);
        }
        __syncthreads();
    }
    float* dst = isQ ? g_Aq : g_As;
#pragma unroll
    for (int j = 0; j < 8; j++)
        dst[(rowBase + r) * C1 + colBase + cg * 8 + j] = acc[j];
}

// ---------------- BN0 factorized stats ---------------------------------------
__global__ void k_bn0stats() {
    int b = blockIdx.x / 12, c = blockIdx.x % 12;
    int o = threadIdx.x;
    if (c < 8) {
        const float* base = g_Aq + (b * QQ + c * 32) * C1 + o;
        float s = 0.f, s2 = 0.f;
#pragma unroll 8
        for (int r = 0; r < 32; r++) {
            float v = base[r * C1];
            s += v; s2 += v * v;
        }
        atomicAdd(&g_bstat[(b * C1 + o) * 4 + 0], s);
        atomicAdd(&g_bstat[(b * C1 + o) * 4 + 1], s2);
    } else {
        const float* base = g_As + (b * SS + (c - 8) * 32) * C1 + o;
        float s = 0.f, s2 = 0.f;
#pragma unroll 8
        for (int r = 0; r < 32; r++) {
            float v = base[r * C1];
            s += v; s2 += v * v;
        }
        atomicAdd(&g_bstat[(b * C1 + o) * 4 + 2], s);
        atomicAdd(&g_bstat[(b * C1 + o) * 4 + 3], s2);
    }
}

__global__ void k_bn0fin(const float* __restrict__ g0, const float* __restrict__ bt0) {
    int o = threadIdx.x;
    float mAA = 0.f, E2 = 0.f;
#pragma unroll
    for (int b = 0; b < BB; b++) {
        const float* p = &g_bstat[(b * C1 + o) * 4];
        float mq = p[0] * (1.f / QQ);
        float ms = p[2] * (1.f / SS);
        mAA += mq + ms;
        E2 += p[1] * (1.f / QQ) + 2.f * mq * ms + p[3] * (1.f / SS);
    }
    mAA *= (1.f / BB);
    E2 *= (1.f / BB);
    float var = E2 - mAA * mAA;
    float sc = g0[o] * rsqrtf(var + EPSB);
    g_sc0[o] = sc;
    g_sh0[o] = bt0[o] - mAA * sc;   // conv bias b0 cancels exactly against BN0 mean
}

// ---------------- apply BN0 affine + pack W1 fragments -----------------------
// blocks [0,128): As transpose. [128,192): Aq affine. [192,200): W1 frag pack.
__global__ void k_prep(const float* __restrict__ W1) {
    int bx = blockIdx.x, tid = threadIdx.x;
    if (bx < 128) {
        __shared__ float tsh[32][33];
        int b = bx >> 5, rem = bx & 31;
        int o0 = (rem >> 2) * 32, s0 = (rem & 3) * 32;
        int wr = tid >> 5, c = tid & 31;
#pragma unroll
        for (int i = 0; i < 4; i++) {
            int r = wr + i * 8;
            tsh[r][c] = g_As[(b * SS + s0 + r) * C1 + o0 + c];
        }
        __syncthreads();
#pragma unroll
        for (int i = 0; i < 4; i++) {
            int r = wr + i * 8;
            g_aspt[(b * C1 + o0 + r) * SS + s0 + c] = tsh[c][r] * g_sc0[o0 + r];
        }
    } else if (bx < 192) {
        int ib = bx - 128;   // 0..63
        const float4* a4 = (const float4*)g_Aq;
        float4* o4p = (float4*)g_aqp;
        const float4* sc4 = (const float4*)g_sc0;
        const float4* sh4 = (const float4*)g_sh0;
#pragma unroll
        for (int k = 0; k < 4; k++) {
            int i = ib * 1024 + k * 256 + tid;
            float4 a = a4[i];
            int oc = i & 63;
            float4 sc = sc4[oc], sh = sh4[oc];
            float4 r;
            r.x = a.x * sc.x + sh.x;
            r.y = a.y * sc.y + sh.y;
            r.z = a.z * sc.z + sh.z;
            r.w = a.w * sc.w + sh.w;
            o4p[i] = r;
        }
    } else {
        // pack W1 into mma B-fragment order:
        // e = ((k8*8 + nt)*32 + lane)*2 + reg ; B(k,j): m = nt*8 + lane/4,
        // o = k8*8 + lane%4 + 4*reg
        int base = (bx - 192) * 2048;
#pragma unroll
        for (int it = 0; it < 8; it++) {
            int e = base + it * 256 + tid;
            int reg = e & 1;
            int lane = (e >> 1) & 31;
            int nt = (e >> 6) & 7;
            int k8 = e >> 9;
            int m = nt * 8 + (lane >> 2);
            int o = k8 * 8 + (lane & 3) + 4 * reg;
            g_w1frag[e] = f2tf(W1[m * C1 + o]);
        }
    }
}

// ---------------- layer 1: mma.sync tf32 GEMM --------------------------------
// Persistent grid=148. Per tile (b,q): D[128 s x 64 m] = X[128x256]*W1^T.
// 8 warps: wr=w>>1 -> mtiles {2wr,2wr+1}; wc=w&1 -> ntiles {4wc..4wc+3}.
extern __shared__ uint32_t sm1[];
__global__ void __launch_bounds__(256, 1)
k_layer1() {
    uint32_t* xs = sm1;                       // [128][XPITCH] tf32 bits
    uint32_t* wf = sm1 + 128 * XPITCH;        // 16384 words, frag order
    float* xsf = (float*)sm1;                 // reuse for D staging
    int tid = threadIdx.x, w = tid >> 5, l = tid & 31;
    int wr = w >> 1, wc = w & 1;

    {   // stage W1 fragments once
        const float4* src = (const float4*)g_w1frag;
        float4* dst = (float4*)wf;
#pragma unroll
        for (int i = 0; i < 16; i++) dst[i * 256 + tid] = src[i * 256 + tid];
    }

    for (int t = blockIdx.x; t < NTILES; t += GRID1) {
        int b = t >> 8;
        const float* asp = g_aspt + b * (C1 * SS) + tid * SS;
        float aqv = g_aqp[t * C1 + tid];
        __syncthreads();   // protect xs from previous tile's readers/epilogue

        // gen X: thread owns o-row = tid; x[s][o] = cvt(relu(aq[o]+as[o][s]))
        {
            const float4* arow = (const float4*)asp;
#pragma unroll 8
            for (int i = 0; i < 32; i++) {
                float4 v = arow[i];
                int s = i * 4;
                xs[(s + 0) * XPITCH + tid] = f2tf(fmaxf(aqv + v.x, 0.f));
                xs[(s + 1) * XPITCH + tid] = f2tf(fmaxf(aqv + v.y, 0.f));
                xs[(s + 2) * XPITCH + tid] = f2tf(fmaxf(aqv + v.z, 0.f));
                xs[(s + 3) * XPITCH + tid] = f2tf(fmaxf(aqv + v.w, 0.f));
            }
        }
        __syncthreads();

        float acc[2][4][4];
#pragma unroll
        for (int mi = 0; mi < 2; mi++)
#pragma unroll
            for (int nt = 0; nt < 4; nt++)
#pragma unroll
                for (int c = 0; c < 4; c++) acc[mi][nt][c] = 0.f;

        int sA = wr * 32 + (l >> 2);
        int oA = l & 3;
#pragma unroll 2
        for (int k8 = 0; k8 < 32; k8++) {
            int ob = k8 * 8 + oA;
            uint32_t a[2][4];
#pragma unroll
            for (int mi = 0; mi < 2; mi++) {
                int s0 = sA + mi * 16;
                a[mi][0] = xs[s0 * XPITCH + ob];
                a[mi][1] = xs[(s0 + 8) * XPITCH + ob];
                a[mi][2] = xs[s0 * XPITCH + ob + 4];
                a[mi][3] = xs[(s0 + 8) * XPITCH + ob + 4];
            }
#pragma unroll
            for (int nt = 0; nt < 4; nt++) {
                int ntg = wc * 4 + nt;
                uint2 bb = *(const uint2*)&wf[((k8 * 8 + ntg) * 32 + l) * 2];
#pragma unroll
                for (int mi = 0; mi < 2; mi++)
                    mma_tf32(acc[mi][nt][0], acc[mi][nt][1], acc[mi][nt][2], acc[mi][nt][3],
                             a[mi][0], a[mi][1], a[mi][2], a[mi][3], bb.x, bb.y);
            }
        }
        __syncthreads();   // xs reads done; stage D into same smem

        {
            int s0 = wr * 32 + (l >> 2);
            int mB = wc * 32 + 2 * (l & 3);
#pragma unroll
            for (int nt = 0; nt < 4; nt++) {
                int m0 = mB + nt * 8;
#pragma unroll
                for (int mi = 0; mi < 2; mi++) {
                    int ss = s0 + mi * 16;
                    xsf[m0 * DPITCH + ss] = acc[mi][nt][0];
                    xsf[(m0 + 1) * DPITCH + ss] = acc[mi][nt][1];
                    xsf[m0 * DPITCH + ss + 8] = acc[mi][nt][2];
                    xsf[(m0 + 1) * DPITCH + ss + 8] = acc[mi][nt][3];
                }
            }
        }
        __syncthreads();

        // coalesced copy-out + BN1 partial sums (warp-uniform m per iteration)
        {
            float* yb = g_y1 + (size_t)t * 128;
#pragma unroll
            for (int it = 0; it < 8; it++) {
                int m = w + 8 * it;
                float4 v = *(const float4*)&xsf[m * DPITCH + 4 * l];
                *(float4*)(yb + (size_t)m * NTOT + 4 * l) = v;
                float s1 = v.x + v.y + v.z + v.w;
                float s2 = v.x * v.x + v.y * v.y + v.z * v.z + v.w * v.w;
#pragma unroll
                for (int d = 16; d > 0; d >>= 1) {
                    s1 += __shfl_xor_sync(0xffffffffu, s1, d);
                    s2 += __shfl_xor_sync(0xffffffffu, s2, d);
                }
                if (l == 0) {
                    atomicAdd(&g_st1[m], s1);
                    atomicAdd(&g_st1[C2 + m], s2);
                }
            }
        }
    }
}

__global__ void k_bn1fin(const float* __restrict__ g1, const float* __restrict__ bt1) {
    int m = threadIdx.x;
    float mean = g_st1[m] * (1.f / NTOT);
    float var = g_st1[C2 + m] * (1.f / NTOT) - mean * mean;
    float sc = g1[m] * rsqrtf(var + EPSB);
    g_sc1[m] = sc;
    g_sh1[m] = bt1[m] - mean * sc;   // conv bias b1 cancels exactly against BN1 mean
}

// ---------------- layer 2 (vectorized) ---------------------------------------
__global__ void k_layer2(const float* __restrict__ W2) {
    __shared__ float sc[C2], sh[C2], w[C2];
    __shared__ float rs[8], rq[8];
    int tid = threadIdx.x;
    if (tid < C2) { sc[tid] = g_sc1[tid]; sh[tid] = g_sh1[tid]; w[tid] = W2[tid]; }
    __syncthreads();
    int n4 = blockIdx.x * 256 + tid;
    const float4* y14 = (const float4*)g_y1;
    float4 acc = make_float4(0.f, 0.f, 0.f, 0.f);
#pragma unroll 8
    for (int m = 0; m < C2; m++) {
        float4 v = y14[(size_t)m * (NTOT / 4) + n4];
        float scm = sc[m], shm = sh[m], wm = w[m];
        acc.x = fmaf(fmaxf(fmaf(v.x, scm, shm), 0.f), wm, acc.x);
        acc.y = fmaf(fmaxf(fmaf(v.y, scm, shm), 0.f), wm, acc.y);
        acc.z = fmaf(fmaxf(fmaf(v.z, scm, shm), 0.f), wm, acc.z);
        acc.w = fmaf(fmaxf(fmaf(v.w, scm, shm), 0.f), wm, acc.w);
    }
    ((float4*)g_y2)[n4] = acc;   // b2 cancels exactly against BN2 mean
    float s1 = acc.x + acc.y + acc.z + acc.w;
    float s2 = acc.x * acc.x + acc.y * acc.y + acc.z * acc.z + acc.w * acc.w;
#pragma unroll
    for (int d = 16; d > 0; d >>= 1) {
        s1 += __shfl_xor_sync(0xffffffffu, s1, d);
        s2 += __shfl_xor_sync(0xffffffffu, s2, d);
    }
    if ((tid & 31) == 0) { rs[tid >> 5] = s1; rq[tid >> 5] = s2; }
    __syncthreads();
    if (tid == 0) {
        float t1 = 0.f, t2 = 0.f;
#pragma unroll
        for (int i = 0; i < 8; i++) { t1 += rs[i]; t2 += rq[i]; }
        atomicAdd(&g_st2[0], t1);
        atomicAdd(&g_st2[1], t2);
    }
}

__global__ void k_bn2fin(const float* __restrict__ g2, const float* __restrict__ bt2) {
    float mean = g_st2[0] * (1.f / NTOT);
    float var = g_st2[1] * (1.f / NTOT) - mean * mean;
    float sc = g2[0] * rsqrtf(var + EPSB);
    g_c2[0] = sc;
    g_c2[1] = bt2[0] - mean * sc;
}

__global__ void k_final(float* __restrict__ out) {
    int n4 = blockIdx.x * 256 + threadIdx.x;
    float sc = g_c2[0], sh = g_c2[1];
    float4 v = ((const float4*)g_y2)[n4];
    float4 r;
    r.x = fmaxf(fmaf(v.x, sc, sh), 0.f);
    r.y = fmaxf(fmaf(v.y, sc, sh), 0.f);
    r.z = fmaxf(fmaf(v.z, sc, sh), 0.f);
    r.w = fmaxf(fmaf(v.w, sc, sh), 0.f);
    ((float4*)out)[n4] = r;
}

// ---------------- launch ------------------------------------------------------
extern "C" void kernel_launch(void* const* d_in, const int* in_sizes, int n_in,
                              void* d_out, int out_size) {
    (void)in_sizes; (void)n_in; (void)out_size;
    const float* support = (const float*)d_in[0];
    const float* query   = (const float*)d_in[1];
    const float* W0  = (const float*)d_in[2];
    // b0, b1, b2 cancel exactly against training-mode BN means; unused.
    const float* g0  = (const float*)d_in[4];
    const float* bt0 = (const float*)d_in[5];
    const float* W1  = (const float*)d_in[6];
    const float* g1  = (const float*)d_in[8];
    const float* bt1 = (const float*)d_in[9];
    const float* W2  = (const float*)d_in[10];
    const float* g2  = (const float*)d_in[12];
    const float* bt2 = (const float*)d_in[13];
    float* out = (float*)d_out;

    size_t smem1 = (size_t)(128 * XPITCH + 32 * 8 * 32 * 2) * 4;  // 198656 B
    cudaFuncSetAttribute(k_layer1, cudaFuncAttributeMaxDynamicSharedMemorySize, (int)smem1);

    dim3 gA(4, 48);
    k_gemmA<<<gA, 256>>>(query, support, W0);
    k_bn0stats<<<BB * 12, 256>>>();
    k_bn0fin<<<1, C1>>>(g0, bt0);
    k_prep<<<200, 256>>>(W1);
    k_layer1<<<GRID1, 256, smem1>>>();
    k_bn1fin<<<1, C2>>>(g1, bt1);
    k_layer2<<<NTOT / 1024, 256>>>(W2);
    k_bn2fin<<<1, 1>>>(g2, bt2);
    k_final<<<NTOT / 1024, 256>>>(out);
}

// round 6
// speedup vs baseline: 2.3156x; 1.3031x over previous
#include <cuda_runtime.h>
#include <cstdint>

#define BB 4
#define QQ 256
#define SS 128
#define CC 256
#define BQ 1024
#define BS 512
#define NTOT 131072
#define C1 256
#define C2 64
#define EPSB 1e-5f
#define GRID1 148
#define NTILES 1024
#define XP1 136     // layer1 X pitch [o][s]: loads conflict-free (136 mod 32 = 8)
#define XPA 260     // gemmA A pitch [m][k]: loads conflict-free (260 mod 32 = 4)
#define DPITCH 132

// ---------------- scratch (static device memory; no allocation) -------------
__device__ float g_Aq[BQ * C1];
__device__ float g_As[BS * C1];
__device__ float g_aspt[BB * C1 * SS];         // As raw, transposed [b][o][s]
__device__ uint32_t g_w0frag[2 * 32 * 32 * 32 * 2]; // W0 tf32 frag [h][k8][ntg][lane][reg]
__device__ uint32_t g_w1frag[32 * 8 * 32 * 2];      // W1 tf32 frag
__device__ float g_y1[C2 * NTOT];
__device__ float g_y2[NTOT];
__device__ float g_bstat[BB * C1 * 4];
__device__ float g_sc0[C1], g_sh0[C1];
__device__ float g_st1[2 * C2];
__device__ float g_st2[2];
__device__ unsigned g_bar1, g_bar2;

// ---------------- helpers ----------------------------------------------------
__device__ __forceinline__ uint32_t f2tf(float f) {
    uint32_t r;
    asm("cvt.rna.tf32.f32 %0, %1;" : "=r"(r) : "f"(f));
    return r;
}
__device__ __forceinline__ void mma_tf32(float& c0, float& c1, float& c2, float& c3,
                                         uint32_t a0, uint32_t a1, uint32_t a2, uint32_t a3,
                                         uint32_t b0, uint32_t b1) {
    asm("mma.sync.aligned.m16n8k8.row.col.f32.tf32.tf32.f32 "
        "{%0,%1,%2,%3}, {%4,%5,%6,%7}, {%8,%9}, {%0,%1,%2,%3};"
        : "+f"(c0), "+f"(c1), "+f"(c2), "+f"(c3)
        : "r"(a0), "r"(a1), "r"(a2), "r"(a3), "r"(b0), "r"(b1));
}
__device__ __forceinline__ void gridbar(unsigned* bar) {
    __threadfence();
    __syncthreads();
    if (threadIdx.x == 0) {
        atomicAdd(bar, 1u);
        while (atomicAdd(bar, 0u) < GRID1) __nanosleep(200);
    }
    __syncthreads();
    __threadfence();
}

// ---------------- pack W0/W1 into mma B-fragment order + zero accums --------
__global__ void k_pack(const float* __restrict__ W0, const float* __restrict__ W1) {
    int bx = blockIdx.x, tid = threadIdx.x;
    if (bx == 0) {
        for (int i = tid; i < BB * C1 * 4; i += 256) g_bstat[i] = 0.f;
        if (tid < 2 * C2) g_st1[tid] = 0.f;
        if (tid < 2) g_st2[tid] = 0.f;
        if (tid == 0) { g_bar1 = 0u; g_bar2 = 0u; }
    }
    if (bx < 64) {
        int base = bx * 2048;
#pragma unroll
        for (int it = 0; it < 8; it++) {
            int e = base + it * 256 + tid;
            int reg = e & 1, l = (e >> 1) & 31, ntg = (e >> 6) & 31;
            int k8 = (e >> 11) & 31, h = e >> 16;
            int m = ntg * 8 + (l >> 2);
            int o = k8 * 8 + (l & 3) + 4 * reg;
            g_w0frag[e] = f2tf(W0[m * (2 * CC) + h * CC + o]);
        }
    } else {
        int base = (bx - 64) * 2048;
#pragma unroll
        for (int it = 0; it < 8; it++) {
            int e = base + it * 256 + tid;
            int reg = e & 1, l = (e >> 1) & 31, nt = (e >> 6) & 7, k8 = e >> 9;
            int m = nt * 8 + (l >> 2);
            int o = k8 * 8 + (l & 3) + 4 * reg;
            g_w1frag[e] = f2tf(W1[m * C1 + o]);
        }
    }
}

// ---------------- gemmA: Aq/As via tf32 mma, BN0 stats folded ----------------
// grid (4 ntb, 12 tm): tm<8 -> Q tiles (128 rows), tm>=8 -> S tiles.
extern __shared__ uint32_t smA[];
__global__ void __launch_bounds__(256, 1)
k_gemmA(const float* __restrict__ query, const float* __restrict__ support) {
    uint32_t* xs = smA;                  // [128][XPA]
    uint32_t* wf = smA + 128 * XPA;      // 16384 words
    int tid = threadIdx.x, w = tid >> 5, l = tid & 31;
    int wr = w >> 1, wc = w & 1;
    int ntb = blockIdx.x, tm = blockIdx.y;
    bool isQ = (tm < 8);
    int rowBase = isQ ? tm * 128 : (tm - 8) * 128;
    const float* inp = (isQ ? query : support) + (size_t)rowBase * CC;
    int h = isQ ? 0 : 1;
    int colBase = ntb * 64;
    int b = isQ ? (tm >> 1) : (tm - 8);

    {   // stage A rows -> tf32 smem [m][k], coalesced
        int m0 = tid >> 6, kc = tid & 63;
#pragma unroll 4
        for (int i = 0; i < 32; i++) {
            int m = m0 + i * 4;
            float4 v = *(const float4*)(inp + m * CC + kc * 4);
            uint4 p;
            p.x = f2tf(v.x); p.y = f2tf(v.y); p.z = f2tf(v.z); p.w = f2tf(v.w);
            *(uint4*)&xs[m * XPA + kc * 4] = p;
        }
    }
    {   // stage this block's W0 fragment slice
        const uint2* src = (const uint2*)g_w0frag;
        uint2* dst = (uint2*)wf;
#pragma unroll 4
        for (int it = 0; it < 32; it++) {
            int j = it * 256 + tid;            // 8192 uint2
            int k8 = j >> 8, ntl = (j >> 5) & 7, ll = j & 31;
            dst[j] = src[((h * 32 + k8) * 32 + ntb * 8 + ntl) * 32 + ll];
        }
    }
    __syncthreads();

    float acc[2][4][4];
#pragma unroll
    for (int mi = 0; mi < 2; mi++)
#pragma unroll
        for (int nt = 0; nt < 4; nt++)
#pragma unroll
            for (int c = 0; c < 4; c++) acc[mi][nt][c] = 0.f;

    int sA = wr * 32 + (l >> 2), oA = l & 3;
#pragma unroll 2
    for (int k8 = 0; k8 < 32; k8++) {
        int ob = k8 * 8 + oA;
        uint32_t a[2][4];
#pragma unroll
        for (int mi = 0; mi < 2; mi++) {
            int s0 = sA + mi * 16;
            a[mi][0] = xs[s0 * XPA + ob];
            a[mi][1] = xs[(s0 + 8) * XPA + ob];
            a[mi][2] = xs[s0 * XPA + ob + 4];
            a[mi][3] = xs[(s0 + 8) * XPA + ob + 4];
        }
#pragma unroll
        for (int nt = 0; nt < 4; nt++) {
            uint2 bb = *(const uint2*)&wf[((k8 * 8 + wc * 4 + nt) * 32 + l) * 2];
#pragma unroll
            for (int mi = 0; mi < 2; mi++)
                mma_tf32(acc[mi][nt][0], acc[mi][nt][1], acc[mi][nt][2], acc[mi][nt][3],
                         a[mi][0], a[mi][1], a[mi][2], a[mi][3], bb.x, bb.y);
        }
    }

    // epilogue: direct STG + BN0 partial sums
    float* dst = isQ ? g_Aq : g_As;
    int qs = isQ ? 0 : 2;
#pragma unroll
    for (int nt = 0; nt < 4; nt++) {
        int m0 = colBase + wc * 32 + nt * 8 + 2 * (l & 3);
        float sum0 = 0.f, sum1 = 0.f, sq0 = 0.f, sq1 = 0.f;
#pragma unroll
        for (int mi = 0; mi < 2; mi++) {
            int s = wr * 32 + (l >> 2) + mi * 16;
            float c0 = acc[mi][nt][0], c1 = acc[mi][nt][1];
            float c2 = acc[mi][nt][2], c3 = acc[mi][nt][3];
            *(float2*)&dst[(rowBase + s) * C1 + m0] = make_float2(c0, c1);
            *(float2*)&dst[(rowBase + s + 8) * C1 + m0] = make_float2(c2, c3);
            sum0 += c0 + c2; sq0 += c0 * c0 + c2 * c2;
            sum1 += c1 + c3; sq1 += c1 * c1 + c3 * c3;
        }
#pragma unroll
        for (int d = 4; d <= 16; d <<= 1) {
            sum0 += __shfl_xor_sync(0xffffffffu, sum0, d);
            sum1 += __shfl_xor_sync(0xffffffffu, sum1, d);
            sq0 += __shfl_xor_sync(0xffffffffu, sq0, d);
            sq1 += __shfl_xor_sync(0xffffffffu, sq1, d);
        }
        if (l < 4) {
            int o = colBase + wc * 32 + nt * 8 + 2 * l;
            atomicAdd(&g_bstat[(b * C1 + o) * 4 + qs], sum0);
            atomicAdd(&g_bstat[(b * C1 + o) * 4 + qs + 1], sq0);
            atomicAdd(&g_bstat[(b * C1 + o + 1) * 4 + qs], sum1);
            atomicAdd(&g_bstat[(b * C1 + o + 1) * 4 + qs + 1], sq1);
        }
    }
}

// ---------------- mid: As transpose (raw) + BN0 finalize ---------------------
__global__ void k_mid(const float* __restrict__ g0, const float* __restrict__ bt0) {
    int bx = blockIdx.x, tid = threadIdx.x;
    if (bx < 128) {
        __shared__ float tsh[32][33];
        int b = bx >> 5, rem = bx & 31;
        int o0 = (rem >> 2) * 32, s0 = (rem & 3) * 32;
        int wr = tid >> 5, c = tid & 31;
#pragma unroll
        for (int i = 0; i < 4; i++) {
            int r = wr + i * 8;
            tsh[r][c] = g_As[(b * SS + s0 + r) * C1 + o0 + c];
        }
        __syncthreads();
#pragma unroll
        for (int i = 0; i < 4; i++) {
            int r = wr + i * 8;
            g_aspt[(b * C1 + o0 + r) * SS + s0 + c] = tsh[c][r];
        }
    } else {
        int o = tid;
        float mAA = 0.f, E2 = 0.f;
#pragma unroll
        for (int b = 0; b < BB; b++) {
            const float* p = &g_bstat[(b * C1 + o) * 4];
            float mq = p[0] * (1.f / QQ);
            float ms = p[2] * (1.f / SS);
            mAA += mq + ms;
            E2 += p[1] * (1.f / QQ) + 2.f * mq * ms + p[3] * (1.f / SS);
        }
        mAA *= (1.f / BB);
        E2 *= (1.f / BB);
        float var = E2 - mAA * mAA;
        float sc = g0[o] * rsqrtf(var + EPSB);
        g_sc0[o] = sc;
        g_sh0[o] = bt0[o] - mAA * sc;   // conv bias b0 cancels exactly
    }
}

// ---------------- layer 1 + fused tail (persistent, 148 CTAs) ----------------
extern __shared__ uint32_t sm1[];
__global__ void __launch_bounds__(256, 1)
k_layer1(const float* __restrict__ g1, const float* __restrict__ bt1,
         const float* __restrict__ W2, const float* __restrict__ g2,
         const float* __restrict__ bt2, float* __restrict__ out) {
    uint32_t* xs = sm1;                    // [256 o][XP1 s] tf32
    uint32_t* wf = sm1 + 256 * XP1;        // 16384 words
    float* xsf = (float*)sm1;              // D staging overlay
    int tid = threadIdx.x, w = tid >> 5, l = tid & 31;
    int wr = w >> 1, wc = w & 1;
    float sc0r = g_sc0[tid], sh0r = g_sh0[tid];

    {   // stage W1 fragments once
        const float4* src = (const float4*)g_w1frag;
        float4* dst = (float4*)wf;
#pragma unroll
        for (int i = 0; i < 16; i++) dst[i * 256 + tid] = src[i * 256 + tid];
    }

    for (int t = blockIdx.x; t < NTILES; t += GRID1) {
        int b = t >> 8;
        float aqv = fmaf(g_Aq[t * C1 + tid], sc0r, sh0r);
        __syncthreads();   // protect xs from previous tile's epilogue reads

        {   // gen X: thread owns o=tid; x[o][s] = cvt(relu(as*sc0 + aq'))
            const float4* arow = (const float4*)(g_aspt + (size_t)(b * C1 + tid) * SS);
#pragma unroll 8
            for (int i = 0; i < 32; i++) {
                float4 v = arow[i];
                uint4 p;
                p.x = f2tf(fmaxf(fmaf(v.x, sc0r, aqv), 0.f));
                p.y = f2tf(fmaxf(fmaf(v.y, sc0r, aqv), 0.f));
                p.z = f2tf(fmaxf(fmaf(v.z, sc0r, aqv), 0.f));
                p.w = f2tf(fmaxf(fmaf(v.w, sc0r, aqv), 0.f));
                *(uint4*)&xs[tid * XP1 + i * 4] = p;
            }
        }
        __syncthreads();

        float acc[2][4][4];
#pragma unroll
        for (int mi = 0; mi < 2; mi++)
#pragma unroll
            for (int nt = 0; nt < 4; nt++)
#pragma unroll
                for (int c = 0; c < 4; c++) acc[mi][nt][c] = 0.f;

        int sA = wr * 32 + (l >> 2), oA = l & 3;
#pragma unroll 2
        for (int k8 = 0; k8 < 32; k8++) {
            int ob = k8 * 8 + oA;
            uint32_t a[2][4];
#pragma unroll
            for (int mi = 0; mi < 2; mi++) {
                int s0 = sA + mi * 16;
                a[mi][0] = xs[ob * XP1 + s0];
                a[mi][1] = xs[ob * XP1 + s0 + 8];
                a[mi][2] = xs[(ob + 4) * XP1 + s0];
                a[mi][3] = xs[(ob + 4) * XP1 + s0 + 8];
            }
#pragma unroll
            for (int nt = 0; nt < 4; nt++) {
                uint2 bb = *(const uint2*)&wf[((k8 * 8 + wc * 4 + nt) * 32 + l) * 2];
#pragma unroll
                for (int mi = 0; mi < 2; mi++)
                    mma_tf32(acc[mi][nt][0], acc[mi][nt][1], acc[mi][nt][2], acc[mi][nt][3],
                             a[mi][0], a[mi][1], a[mi][2], a[mi][3], bb.x, bb.y);
            }
        }
        __syncthreads();   // xs reads done; stage D

        {
            int s0 = wr * 32 + (l >> 2);
            int mB = wc * 32 + 2 * (l & 3);
#pragma unroll
            for (int nt = 0; nt < 4; nt++) {
                int m0 = mB + nt * 8;
#pragma unroll
                for (int mi = 0; mi < 2; mi++) {
                    int ss = s0 + mi * 16;
                    xsf[m0 * DPITCH + ss] = acc[mi][nt][0];
                    xsf[(m0 + 1) * DPITCH + ss] = acc[mi][nt][1];
                    xsf[m0 * DPITCH + ss + 8] = acc[mi][nt][2];
                    xsf[(m0 + 1) * DPITCH + ss + 8] = acc[mi][nt][3];
                }
            }
        }
        __syncthreads();

        {   // coalesced copy-out + BN1 partial sums
            float* yb = g_y1 + (size_t)t * 128;
#pragma unroll
            for (int it = 0; it < 8; it++) {
                int m = w + 8 * it;
                float4 v = *(const float4*)&xsf[m * DPITCH + 4 * l];
                *(float4*)(yb + (size_t)m * NTOT + 4 * l) = v;
                float s1 = v.x + v.y + v.z + v.w;
                float s2 = v.x * v.x + v.y * v.y + v.z * v.z + v.w * v.w;
#pragma unroll
                for (int d = 16; d > 0; d >>= 1) {
                    s1 += __shfl_xor_sync(0xffffffffu, s1, d);
                    s2 += __shfl_xor_sync(0xffffffffu, s2, d);
                }
                if (l == 0) {
                    atomicAdd(&g_st1[m], s1);
                    atomicAdd(&g_st1[C2 + m], s2);
                }
            }
        }
    }

    // ---------------- fused tail ----------------
    gridbar(&g_bar1);

    float* sc1s = (float*)sm1;
    float* sh1s = sc1s + C2;
    float* w2s = sh1s + C2;
    if (tid < C2) {
        float mean = g_st1[tid] * (1.f / NTOT);
        float var = g_st1[C2 + tid] * (1.f / NTOT) - mean * mean;
        float sc = g1[tid] * rsqrtf(var + EPSB);
        sc1s[tid] = sc;
        sh1s[tid] = bt1[tid] - mean * sc;  // conv bias b1 cancels exactly
        w2s[tid] = W2[tid];
    }
    __syncthreads();

    int idx = blockIdx.x * 256 + tid;
    if (idx < NTOT / 4) {
        const float4* y14 = (const float4*)g_y1;
        float4 acc = make_float4(0.f, 0.f, 0.f, 0.f);
#pragma unroll 8
        for (int m = 0; m < C2; m++) {
            float4 v = y14[(size_t)m * (NTOT / 4) + idx];
            float scm = sc1s[m], shm = sh1s[m], wm = w2s[m];
            acc.x = fmaf(fmaxf(fmaf(v.x, scm, shm), 0.f), wm, acc.x);
            acc.y = fmaf(fmaxf(fmaf(v.y, scm, shm), 0.f), wm, acc.y);
            acc.z = fmaf(fmaxf(fmaf(v.z, scm, shm), 0.f), wm, acc.z);
            acc.w = fmaf(fmaxf(fmaf(v.w, scm, shm), 0.f), wm, acc.w);
        }
        ((float4*)g_y2)[idx] = acc;   // b2 cancels exactly
        float s1 = acc.x + acc.y + acc.z + acc.w;
        float s2 = acc.x * acc.x + acc.y * acc.y + acc.z * acc.z + acc.w * acc.w;
#pragma unroll
        for (int d = 16; d > 0; d >>= 1) {
            s1 += __shfl_xor_sync(0xffffffffu, s1, d);
            s2 += __shfl_xor_sync(0xffffffffu, s2, d);
        }
        if (l == 0) {
            atomicAdd(&g_st2[0], s1);
            atomicAdd(&g_st2[1], s2);
        }
    }

    gridbar(&g_bar2);

    if (idx < NTOT / 4) {
        float mean = g_st2[0] * (1.f / NTOT);
        float var = g_st2[1] * (1.f / NTOT) - mean * mean;
        float sc = g2[0] * rsqrtf(var + EPSB);
        float sh = bt2[0] - mean * sc;   // conv bias b2 cancels exactly
        float4 v = ((const float4*)g_y2)[idx];
        float4 r;
        r.x = fmaxf(fmaf(v.x, sc, sh), 0.f);
        r.y = fmaxf(fmaf(v.y, sc, sh), 0.f);
        r.z = fmaxf(fmaf(v.z, sc, sh), 0.f);
        r.w = fmaxf(fmaf(v.w, sc, sh), 0.f);
        ((float4*)out)[idx] = r;
    }
}

// ---------------- launch ------------------------------------------------------
extern "C" void kernel_launch(void* const* d_in, const int* in_sizes, int n_in,
                              void* d_out, int out_size) {
    (void)in_sizes; (void)n_in; (void)out_size;
    const float* support = (const float*)d_in[0];
    const float* query   = (const float*)d_in[1];
    const float* W0  = (const float*)d_in[2];
    // b0, b1, b2 cancel exactly against training-mode BN means; unused.
    const float* g0  = (const float*)d_in[4];
    const float* bt0 = (const float*)d_in[5];
    const float* W1  = (const float*)d_in[6];
    const float* g1  = (const float*)d_in[8];
    const float* bt1 = (const float*)d_in[9];
    const float* W2  = (const float*)d_in[10];
    const float* g2  = (const float*)d_in[12];
    const float* bt2 = (const float*)d_in[13];
    float* out = (float*)d_out;

    size_t smemA = (size_t)(128 * XPA + 16384) * 4;   // 198656 B
    size_t smem1 = (size_t)(256 * XP1 + 16384) * 4;   // 204800 B
    cudaFuncSetAttribute(k_gemmA, cudaFuncAttributeMaxDynamicSharedMemorySize, (int)smemA);
    cudaFuncSetAttribute(k_layer1, cudaFuncAttributeMaxDynamicSharedMemorySize, (int)smem1);

    k_pack<<<72, 256>>>(W0, W1);
    dim3 gA(4, 12);
    k_gemmA<<<gA, 256, smemA>>>(query, support);
    k_mid<<<129, 256>>>(g0, bt0);
    k_layer1<<<GRID1, 256, smem1>>>(g1, bt1, W2, g2, bt2, out);
}

// round 8
// speedup vs baseline: 2.6047x; 1.1248x over previous
#include <cuda_runtime.h>
#include <cstdint>

#define BB 4
#define QQ 256
#define SS 128
#define CC 256
#define BQ 1024
#define BS 512
#define NTOT 131072
#define C1 256
#define C2 64
#define EPSB 1e-5f
#define GRID1 148
#define NTILES 1024
#define XP1 136     // layer1 X pitch [o][s]: 136 mod 32 = 8 -> conflict-free A loads
#define XPA 260     // gemmA A pitch
#define DPITCH 132
#define T1 512      // layer1 threads

// ---------------- scratch (static device memory; no allocation) -------------
__device__ float g_Aq[BQ * C1];
__device__ float g_As[BS * C1];
__device__ float g_aspt[BB * C1 * SS];              // As raw, transposed [b][o][s]
__device__ uint32_t g_w0frag[2 * 32 * 32 * 32 * 2]; // W0 tf32 frag
__device__ uint32_t g_w1frag[32 * 2 * 2 * 32 * 4];  // W1 tf32 frag [k8][wc][h][lane][4]
__device__ float g_y1[C2 * NTOT];
__device__ float g_y2[NTOT];
__device__ float g_bstat[BB * C1 * 4];
__device__ float g_sc0[C1], g_sh0[C1];
__device__ float g_st1[2 * C2];
__device__ float g_st2[2];
__device__ unsigned g_bar1, g_bar2;

// ---------------- helpers ----------------------------------------------------
__device__ __forceinline__ uint32_t f2tf(float f) {
    uint32_t r;
    asm("cvt.rna.tf32.f32 %0, %1;" : "=r"(r) : "f"(f));
    return r;
}
__device__ __forceinline__ void mma_tf32(float& c0, float& c1, float& c2, float& c3,
                                         uint32_t a0, uint32_t a1, uint32_t a2, uint32_t a3,
                                         uint32_t b0, uint32_t b1) {
    asm("mma.sync.aligned.m16n8k8.row.col.f32.tf32.tf32.f32 "
        "{%0,%1,%2,%3}, {%4,%5,%6,%7}, {%8,%9}, {%0,%1,%2,%3};"
        : "+f"(c0), "+f"(c1), "+f"(c2), "+f"(c3)
        : "r"(a0), "r"(a1), "r"(a2), "r"(a3), "r"(b0), "r"(b1));
}
__device__ __forceinline__ void gridbar(unsigned* bar) {
    __threadfence();
    __syncthreads();
    if (threadIdx.x == 0) {
        atomicAdd(bar, 1u);
        while (atomicAdd(bar, 0u) < GRID1) __nanosleep(200);
    }
    __syncthreads();
    __threadfence();
}

// ---------------- pack W0/W1 into fragment order + zero accums ---------------
__global__ void k_pack(const float* __restrict__ W0, const float* __restrict__ W1) {
    int bx = blockIdx.x, tid = threadIdx.x;
    if (bx == 0) {
        for (int i = tid; i < BB * C1 * 4; i += 256) g_bstat[i] = 0.f;
        if (tid < 2 * C2) g_st1[tid] = 0.f;
        if (tid < 2) g_st2[tid] = 0.f;
        if (tid == 0) { g_bar1 = 0u; g_bar2 = 0u; }
    }
    if (bx < 64) {
        int base = bx * 2048;
#pragma unroll
        for (int it = 0; it < 8; it++) {
            int e = base + it * 256 + tid;
            int reg = e & 1, l = (e >> 1) & 31, ntg = (e >> 6) & 31;
            int k8 = (e >> 11) & 31, h = e >> 16;
            int m = ntg * 8 + (l >> 2);
            int o = k8 * 8 + (l & 3) + 4 * reg;
            g_w0frag[e] = f2tf(W0[m * (2 * CC) + h * CC + o]);
        }
    } else {
        // W1 frag: e = (((k8*2+wc)*2+h)*32+l)*4 + r4; nt = 2h + (r4>>1); reg = r4&1
        int base = (bx - 64) * 2048;
#pragma unroll
        for (int it = 0; it < 8; it++) {
            int e = base + it * 256 + tid;
            int r4 = e & 3, l = (e >> 2) & 31, h = (e >> 7) & 1;
            int wc = (e >> 8) & 1, k8 = e >> 9;
            int nt = 2 * h + (r4 >> 1), reg = r4 & 1;
            int m = (wc * 4 + nt) * 8 + (l >> 2);
            int o = k8 * 8 + (l & 3) + 4 * reg;
            g_w1frag[e] = f2tf(W1[m * C1 + o]);
        }
    }
}

// ---------------- gemmA: Aq/As via tf32 mma, BN0 stats folded ----------------
extern __shared__ uint32_t smA[];
__global__ void __launch_bounds__(256, 1)
k_gemmA(const float* __restrict__ query, const float* __restrict__ support) {
    uint32_t* xs = smA;                  // [128][XPA]
    uint32_t* wf = smA + 128 * XPA;      // 16384 words
    int tid = threadIdx.x, w = tid >> 5, l = tid & 31;
    int wr = w >> 1, wc = w & 1;
    int ntb = blockIdx.x, tm = blockIdx.y;
    bool isQ = (tm < 8);
    int rowBase = isQ ? tm * 128 : (tm - 8) * 128;
    const float* inp = (isQ ? query : support) + (size_t)rowBase * CC;
    int h = isQ ? 0 : 1;
    int colBase = ntb * 64;
    int b = isQ ? (tm >> 1) : (tm - 8);

    {
        int m0 = tid >> 6, kc = tid & 63;
#pragma unroll 4
        for (int i = 0; i < 32; i++) {
            int m = m0 + i * 4;
            float4 v = *(const float4*)(inp + m * CC + kc * 4);
            uint4 p;
            p.x = f2tf(v.x); p.y = f2tf(v.y); p.z = f2tf(v.z); p.w = f2tf(v.w);
            *(uint4*)&xs[m * XPA + kc * 4] = p;
        }
    }
    {
        const uint2* src = (const uint2*)g_w0frag;
        uint2* dst = (uint2*)wf;
#pragma unroll 4
        for (int it = 0; it < 32; it++) {
            int j = it * 256 + tid;
            int k8 = j >> 8, ntl = (j >> 5) & 7, ll = j & 31;
            dst[j] = src[((h * 32 + k8) * 32 + ntb * 8 + ntl) * 32 + ll];
        }
    }
    __syncthreads();

    float acc[2][4][4];
#pragma unroll
    for (int mi = 0; mi < 2; mi++)
#pragma unroll
        for (int nt = 0; nt < 4; nt++)
#pragma unroll
            for (int c = 0; c < 4; c++) acc[mi][nt][c] = 0.f;

    int sA = wr * 32 + (l >> 2), oA = l & 3;
#pragma unroll 2
    for (int k8 = 0; k8 < 32; k8++) {
        int ob = k8 * 8 + oA;
        uint32_t a[2][4];
#pragma unroll
        for (int mi = 0; mi < 2; mi++) {
            int s0 = sA + mi * 16;
            a[mi][0] = xs[s0 * XPA + ob];
            a[mi][1] = xs[(s0 + 8) * XPA + ob];
            a[mi][2] = xs[s0 * XPA + ob + 4];
            a[mi][3] = xs[(s0 + 8) * XPA + ob + 4];
        }
#pragma unroll
        for (int nt = 0; nt < 4; nt++) {
            uint2 bb = *(const uint2*)&wf[((k8 * 8 + wc * 4 + nt) * 32 + l) * 2];
#pragma unroll
            for (int mi = 0; mi < 2; mi++)
                mma_tf32(acc[mi][nt][0], acc[mi][nt][1], acc[mi][nt][2], acc[mi][nt][3],
                         a[mi][0], a[mi][1], a[mi][2], a[mi][3], bb.x, bb.y);
        }
    }

    float* dst = isQ ? g_Aq : g_As;
    int qs = isQ ? 0 : 2;
#pragma unroll
    for (int nt = 0; nt < 4; nt++) {
        int m0 = colBase + wc * 32 + nt * 8 + 2 * (l & 3);
        float sum0 = 0.f, sum1 = 0.f, sq0 = 0.f, sq1 = 0.f;
#pragma unroll
        for (int mi = 0; mi < 2; mi++) {
            int s = wr * 32 + (l >> 2) + mi * 16;
            float c0 = acc[mi][nt][0], c1 = acc[mi][nt][1];
            float c2 = acc[mi][nt][2], c3 = acc[mi][nt][3];
            *(float2*)&dst[(rowBase + s) * C1 + m0] = make_float2(c0, c1);
            *(float2*)&dst[(rowBase + s + 8) * C1 + m0] = make_float2(c2, c3);
            sum0 += c0 + c2; sq0 += c0 * c0 + c2 * c2;
            sum1 += c1 + c3; sq1 += c1 * c1 + c3 * c3;
        }
#pragma unroll
        for (int d = 4; d <= 16; d <<= 1) {
            sum0 += __shfl_xor_sync(0xffffffffu, sum0, d);
            sum1 += __shfl_xor_sync(0xffffffffu, sum1, d);
            sq0 += __shfl_xor_sync(0xffffffffu, sq0, d);
            sq1 += __shfl_xor_sync(0xffffffffu, sq1, d);
        }
        if (l < 4) {
            int o = colBase + wc * 32 + nt * 8 + 2 * l;
            atomicAdd(&g_bstat[(b * C1 + o) * 4 + qs], sum0);
            atomicAdd(&g_bstat[(b * C1 + o) * 4 + qs + 1], sq0);
            atomicAdd(&g_bstat[(b * C1 + o + 1) * 4 + qs], sum1);
            atomicAdd(&g_bstat[(b * C1 + o + 1) * 4 + qs + 1], sq1);
        }
    }
}

// ---------------- mid: As transpose + BN0 finalize ---------------------------
__global__ void k_mid(const float* __restrict__ g0, const float* __restrict__ bt0) {
    int bx = blockIdx.x, tid = threadIdx.x;
    if (bx < 128) {
        __shared__ float tsh[32][33];
        int b = bx >> 5, rem = bx & 31;
        int o0 = (rem >> 2) * 32, s0 = (rem & 3) * 32;
        int wr = tid >> 5, c = tid & 31;
#pragma unroll
        for (int i = 0; i < 4; i++) {
            int r = wr + i * 8;
            tsh[r][c] = g_As[(b * SS + s0 + r) * C1 + o0 + c];
        }
        __syncthreads();
#pragma unroll
        for (int i = 0; i < 4; i++) {
            int r = wr + i * 8;
            g_aspt[(b * C1 + o0 + r) * SS + s0 + c] = tsh[c][r];
        }
    } else {
        int o = tid;
        float mAA = 0.f, E2 = 0.f;
#pragma unroll
        for (int b = 0; b < BB; b++) {
            const float* p = &g_bstat[(b * C1 + o) * 4];
            float mq = p[0] * (1.f / QQ);
            float ms = p[2] * (1.f / SS);
            mAA += mq + ms;
            E2 += p[1] * (1.f / QQ) + 2.f * mq * ms + p[3] * (1.f / SS);
        }
        mAA *= (1.f / BB);
        E2 *= (1.f / BB);
        float var = E2 - mAA * mAA;
        float sc = g0[o] * rsqrtf(var + EPSB);
        g_sc0[o] = sc;
        g_sh0[o] = bt0[o] - mAA * sc;   // conv bias b0 cancels exactly
    }
}

// ---------------- layer 1 + fused tail (persistent, 148 CTAs, 512 thr) -------
extern __shared__ uint32_t sm1[];
__global__ void __launch_bounds__(T1, 1)
k_layer1(const float* __restrict__ g1, const float* __restrict__ bt1,
         const float* __restrict__ W2, const float* __restrict__ g2,
         const float* __restrict__ bt2, float* __restrict__ out) {
    uint32_t* xs = sm1;                    // [256 o][XP1 s] tf32
    uint32_t* wf = sm1 + 256 * XP1;        // 16384 words frag order
    float* xsf = (float*)sm1;              // D staging overlay
    int tid = threadIdx.x, w = tid >> 5, l = tid & 31;
    int wr = w >> 1, wc = w & 1;           // wr: s-chunk 0..7, wc: m-half
    int og = tid >> 1, oh = tid & 1;       // gen: thread owns o=og, 16B-interleave oh
    float sc0r = g_sc0[og], sh0r = g_sh0[og];

    {   // stage W1 fragments once
        const uint4* src = (const uint4*)g_w1frag;
        uint4* dst = (uint4*)wf;
#pragma unroll
        for (int i = 0; i < 8; i++) dst[i * T1 + tid] = src[i * T1 + tid];
    }

    const uint4* wf4 = (const uint4*)wf;
    int s0 = wr * 16 + (l >> 2), oA = l & 3;

    for (int t = blockIdx.x; t < NTILES; t += GRID1) {
        int b = t >> 8;
        float aqv = fmaf(g_Aq[t * C1 + og], sc0r, sh0r);
        __syncthreads();   // protect xs/wf from previous phase readers

        {   // gen X: x[o][s] = cvt(relu(as*sc0 + aq')), 16B interleave per pair
            const float4* arow = (const float4*)(g_aspt + (size_t)(b * C1 + og) * SS);
            uint32_t* xrow = &xs[og * XP1];
#pragma unroll 8
            for (int i = 0; i < 16; i++) {
                int j = oh + 2 * i;
                float4 v = arow[j];
                uint4 p;
                p.x = f2tf(fmaxf(fmaf(v.x, sc0r, aqv), 0.f));
                p.y = f2tf(fmaxf(fmaf(v.y, sc0r, aqv), 0.f));
                p.z = f2tf(fmaxf(fmaf(v.z, sc0r, aqv), 0.f));
                p.w = f2tf(fmaxf(fmaf(v.w, sc0r, aqv), 0.f));
                *(uint4*)&xrow[j * 4] = p;
            }
        }
        __syncthreads();

        float acc[4][4];
#pragma unroll
        for (int nt = 0; nt < 4; nt++)
#pragma unroll
            for (int c = 0; c < 4; c++) acc[nt][c] = 0.f;

        uint32_t aC[4];
        uint4 bC0, bC1;
        {   // prefetch k8=0
            aC[0] = xs[oA * XP1 + s0];
            aC[1] = xs[oA * XP1 + s0 + 8];
            aC[2] = xs[(oA + 4) * XP1 + s0];
            aC[3] = xs[(oA + 4) * XP1 + s0 + 8];
            bC0 = wf4[(wc * 2) * 32 + l];
            bC1 = wf4[(wc * 2 + 1) * 32 + l];
        }
#pragma unroll
        for (int k8 = 0; k8 < 32; k8++) {
            uint32_t aN[4];
            uint4 bN0, bN1;
            if (k8 < 31) {
                int ob = (k8 + 1) * 8 + oA;
                aN[0] = xs[ob * XP1 + s0];
                aN[1] = xs[ob * XP1 + s0 + 8];
                aN[2] = xs[(ob + 4) * XP1 + s0];
                aN[3] = xs[(ob + 4) * XP1 + s0 + 8];
                bN0 = wf4[(((k8 + 1) * 2 + wc) * 2) * 32 + l];
                bN1 = wf4[(((k8 + 1) * 2 + wc) * 2 + 1) * 32 + l];
            }
            mma_tf32(acc[0][0], acc[0][1], acc[0][2], acc[0][3],
                     aC[0], aC[1], aC[2], aC[3], bC0.x, bC0.y);
            mma_tf32(acc[1][0], acc[1][1], acc[1][2], acc[1][3],
                     aC[0], aC[1], aC[2], aC[3], bC0.z, bC0.w);
            mma_tf32(acc[2][0], acc[2][1], acc[2][2], acc[2][3],
                     aC[0], aC[1], aC[2], aC[3], bC1.x, bC1.y);
            mma_tf32(acc[3][0], acc[3][1], acc[3][2], acc[3][3],
                     aC[0], aC[1], aC[2], aC[3], bC1.z, bC1.w);
            if (k8 < 31) {
                aC[0] = aN[0]; aC[1] = aN[1]; aC[2] = aN[2]; aC[3] = aN[3];
                bC0 = bN0; bC1 = bN1;
            }
        }
        __syncthreads();   // xs reads done; stage D

        {
            int mB = wc * 32 + 2 * (l & 3);
#pragma unroll
            for (int nt = 0; nt < 4; nt++) {
                int m0 = mB + nt * 8;
                xsf[m0 * DPITCH + s0] = acc[nt][0];
                xsf[(m0 + 1) * DPITCH + s0] = acc[nt][1];
                xsf[m0 * DPITCH + s0 + 8] = acc[nt][2];
                xsf[(m0 + 1) * DPITCH + s0 + 8] = acc[nt][3];
            }
        }
        __syncthreads();

        {   // coalesced copy-out + BN1 partial sums (warp-uniform m)
            float* yb = g_y1 + (size_t)t * 128;
#pragma unroll
            for (int it = 0; it < 4; it++) {
                int m = w + 16 * it;
                float4 v = *(const float4*)&xsf[m * DPITCH + 4 * l];
                *(float4*)(yb + (size_t)m * NTOT + 4 * l) = v;
                float s1 = v.x + v.y + v.z + v.w;
                float s2 = v.x * v.x + v.y * v.y + v.z * v.z + v.w * v.w;
#pragma unroll
                for (int d = 16; d > 0; d >>= 1) {
                    s1 += __shfl_xor_sync(0xffffffffu, s1, d);
                    s2 += __shfl_xor_sync(0xffffffffu, s2, d);
                }
                if (l == 0) {
                    atomicAdd(&g_st1[m], s1);
                    atomicAdd(&g_st1[C2 + m], s2);
                }
            }
        }
    }

    // ---------------- fused tail ----------------
    gridbar(&g_bar1);

    float* sc1s = (float*)sm1;
    float* sh1s = sc1s + C2;
    float* w2s = sh1s + C2;
    if (tid < C2) {
        float mean = g_st1[tid] * (1.f / NTOT);
        float var = g_st1[C2 + tid] * (1.f / NTOT) - mean * mean;
        float sc = g1[tid] * rsqrtf(var + EPSB);
        sc1s[tid] = sc;
        sh1s[tid] = bt1[tid] - mean * sc;  // conv bias b1 cancels exactly
        w2s[tid] = W2[tid];
    }
    __syncthreads();

    int idx = blockIdx.x * T1 + tid;
    if (idx < NTOT / 4) {
        const float4* y14 = (const float4*)g_y1;
        float4 acc = make_float4(0.f, 0.f, 0.f, 0.f);
#pragma unroll 8
        for (int m = 0; m < C2; m++) {
            float4 v = y14[(size_t)m * (NTOT / 4) + idx];
            float scm = sc1s[m], shm = sh1s[m], wm = w2s[m];
            acc.x = fmaf(fmaxf(fmaf(v.x, scm, shm), 0.f), wm, acc.x);
            acc.y = fmaf(fmaxf(fmaf(v.y, scm, shm), 0.f), wm, acc.y);
            acc.z = fmaf(fmaxf(fmaf(v.z, scm, shm), 0.f), wm, acc.z);
            acc.w = fmaf(fmaxf(fmaf(v.w, scm, shm), 0.f), wm, acc.w);
        }
        ((float4*)g_y2)[idx] = acc;   // b2 cancels exactly
        float s1 = acc.x + acc.y + acc.z + acc.w;
        float s2 = acc.x * acc.x + acc.y * acc.y + acc.z * acc.z + acc.w * acc.w;
#pragma unroll
        for (int d = 16; d > 0; d >>= 1) {
            s1 += __shfl_xor_sync(0xffffffffu, s1, d);
            s2 += __shfl_xor_sync(0xffffffffu, s2, d);
        }
        if (l == 0) {
            atomicAdd(&g_st2[0], s1);
            atomicAdd(&g_st2[1], s2);
        }
    }

    gridbar(&g_bar2);

    if (idx < NTOT / 4) {
        float mean = g_st2[0] * (1.f / NTOT);
        float var = g_st2[1] * (1.f / NTOT) - mean * mean;
        float sc = g2[0] * rsqrtf(var + EPSB);
        float sh = bt2[0] - mean * sc;   // conv bias b2 cancels exactly
        float4 v = ((const float4*)g_y2)[idx];
        float4 r;
        r.x = fmaxf(fmaf(v.x, sc, sh), 0.f);
        r.y = fmaxf(fmaf(v.y, sc, sh), 0.f);
        r.z = fmaxf(fmaf(v.z, sc, sh), 0.f);
        r.w = fmaxf(fmaf(v.w, sc, sh), 0.f);
        ((float4*)out)[idx] = r;
    }
}

// ---------------- launch ------------------------------------------------------
extern "C" void kernel_launch(void* const* d_in, const int* in_sizes, int n_in,
                              void* d_out, int out_size) {
    (void)in_sizes; (void)n_in; (void)out_size;
    const float* support = (const float*)d_in[0];
    const float* query   = (const float*)d_in[1];
    const float* W0  = (const float*)d_in[2];
    // b0, b1, b2 cancel exactly against training-mode BN means; unused.
    const float* g0  = (const float*)d_in[4];
    const float* bt0 = (const float*)d_in[5];
    const float* W1  = (const float*)d_in[6];
    const float* g1  = (const float*)d_in[8];
    const float* bt1 = (const float*)d_in[9];
    const float* W2  = (const float*)d_in[10];
    const float* g2  = (const float*)d_in[12];
    const float* bt2 = (const float*)d_in[13];
    float* out = (float*)d_out;

    size_t smemA = (size_t)(128 * XPA + 16384) * 4;   // 198656 B
    size_t smem1 = (size_t)(256 * XP1 + 16384) * 4;   // 204800 B
    cudaFuncSetAttribute(k_gemmA, cudaFuncAttributeMaxDynamicSharedMemorySize, (int)smemA);
    cudaFuncSetAttribute(k_layer1, cudaFuncAttributeMaxDynamicSharedMemorySize, (int)smem1);

    k_pack<<<72, 256>>>(W0, W1);
    dim3 gA(4, 12);
    k_gemmA<<<gA, 256, smemA>>>(query, support);
    k_mid<<<129, 256>>>(g0, bt0);
    k_layer1<<<GRID1, T1, smem1>>>(g1, bt1, W2, g2, bt2, out);
}